// round 7
// baseline (speedup 1.0000x reference)
#include <cuda_runtime.h>
#include <cuda_bf16.h>

// ForwardKinematics: B=524288, NA=7 joints, NJ=8 transforms.
// out[n] = M0*...*M6*F7, Mi = Fi*[[R(theta_i,a_i),0],[0,1]]
// rot(Mi) = A_i + sin*(A_i K_i) + (1-cos)*(A_i(aa^T) - A_i); trans(Mi)=t_i.
//
// R7: latency-bound (issue% tracks occ%; stall gap ~15cyc/warp). Break the
// serial 7-deep chain into a 3-deep balanced tree of affine products with
// wide ILP; fold F7 into joint-6 constants; f32x2 packed pairs (g, g+n/2);
// smem-staged coalesced input; 128-thread blocks for regfile granularity.

#define NACT 7
#define THREADS 128

typedef unsigned long long u64;

__device__ __forceinline__ u64 fma2(u64 a, u64 b, u64 c) {
    u64 d; asm("fma.rn.f32x2 %0, %1, %2, %3;" : "=l"(d) : "l"(a), "l"(b), "l"(c)); return d;
}
__device__ __forceinline__ u64 mul2(u64 a, u64 b) {
    u64 d; asm("mul.rn.f32x2 %0, %1, %2;" : "=l"(d) : "l"(a), "l"(b)); return d;
}
__device__ __forceinline__ u64 pack2(float lo, float hi) {
    u64 d; asm("mov.b64 %0, {%1, %2};" : "=l"(d) : "f"(lo), "f"(hi)); return d;
}
__device__ __forceinline__ float2 unpack2(u64 v) {
    float lo, hi; asm("mov.b64 {%0, %1}, %2;" : "=f"(lo), "=f"(hi) : "l"(v));
    return make_float2(lo, hi);
}

// affine multiply: X = Y * Z  (3x3 rot + 3 trans, implicit [0 0 0 1] row)
__device__ __forceinline__ void amul(const u64* Yr, const u64* Yt,
                                     const u64* Zr, const u64* Zt,
                                     u64* Xr, u64* Xt) {
    #pragma unroll
    for (int r = 0; r < 3; r++) {
        #pragma unroll
        for (int c = 0; c < 3; c++)
            Xr[r * 3 + c] = fma2(Yr[r * 3 + 2], Zr[6 + c],
                            fma2(Yr[r * 3 + 1], Zr[3 + c],
                            mul2(Yr[r * 3 + 0], Zr[c])));
        Xt[r] = fma2(Yr[r * 3 + 2], Zt[2],
                fma2(Yr[r * 3 + 1], Zt[1],
                fma2(Yr[r * 3 + 0], Zt[0], Yt[r])));
    }
}

// build Mi (joints 0..5): rot = A + s*B + o*C from splatted smem, trans = const t
__device__ __forceinline__ void buildM(const float2* pA, const float2* pB,
                                       const float2* pC, const float2* pT,
                                       float t0, float t1, u64* Mr, u64* Mt) {
    float s0, c0, s1, c1;
    __sincosf(t0, &s0, &c0);
    __sincosf(t1, &s1, &c1);
    u64 s2 = pack2(s0, s1);
    u64 o2 = pack2(1.0f - c0, 1.0f - c1);
    const ulonglong2* Av = reinterpret_cast<const ulonglong2*>(pA);
    const ulonglong2* Bv = reinterpret_cast<const ulonglong2*>(pB);
    const ulonglong2* Cv = reinterpret_cast<const ulonglong2*>(pC);
    #pragma unroll
    for (int kp = 0; kp < 4; kp++) {
        ulonglong2 a = Av[kp], b = Bv[kp], c = Cv[kp];
        Mr[2 * kp + 0] = fma2(o2, c.x, fma2(s2, b.x, a.x));
        Mr[2 * kp + 1] = fma2(o2, c.y, fma2(s2, b.y, a.y));
    }
    {
        ulonglong2 a = Av[4], b = Bv[4], c = Cv[4];
        Mr[8] = fma2(o2, c.x, fma2(s2, b.x, a.x));
    }
    const ulonglong2* Tv = reinterpret_cast<const ulonglong2*>(pT);
    ulonglong2 t01 = Tv[0], t23 = Tv[1];
    Mt[0] = t01.x; Mt[1] = t01.y; Mt[2] = t23.x;
}

// build M6' = M6*F7: rot = A' + s*B' + o*C'; trans = a't + s*b't + o*c't
__device__ __forceinline__ void buildM6(const float2* pA, const float2* pB,
                                        const float2* pC, const float2* pT6,
                                        float t0, float t1, u64* Mr, u64* Mt) {
    float s0, c0, s1, c1;
    __sincosf(t0, &s0, &c0);
    __sincosf(t1, &s1, &c1);
    u64 s2 = pack2(s0, s1);
    u64 o2 = pack2(1.0f - c0, 1.0f - c1);
    const ulonglong2* Av = reinterpret_cast<const ulonglong2*>(pA);
    const ulonglong2* Bv = reinterpret_cast<const ulonglong2*>(pB);
    const ulonglong2* Cv = reinterpret_cast<const ulonglong2*>(pC);
    #pragma unroll
    for (int kp = 0; kp < 4; kp++) {
        ulonglong2 a = Av[kp], b = Bv[kp], c = Cv[kp];
        Mr[2 * kp + 0] = fma2(o2, c.x, fma2(s2, b.x, a.x));
        Mr[2 * kp + 1] = fma2(o2, c.y, fma2(s2, b.y, a.y));
    }
    {
        ulonglong2 a = Av[4], b = Bv[4], c = Cv[4];
        Mr[8] = fma2(o2, c.x, fma2(s2, b.x, a.x));
    }
    const u64* t6 = reinterpret_cast<const u64*>(pT6);  // [0..2]=a't [3..5]=b't [6..8]=c't
    #pragma unroll
    for (int r = 0; r < 3; r++)
        Mt[r] = fma2(o2, t6[6 + r], fma2(s2, t6[3 + r], t6[r]));
}

__global__ __launch_bounds__(THREADS)
void fk_kernel(const float* __restrict__ jp,    // (B,7)
               const float* __restrict__ ft,    // (8,4,4)
               const float* __restrict__ axes,  // (7,3)
               float* __restrict__ out,         // (B,4,4)
               int n)
{
    __shared__ alignas(16) float s_in[2 * THREADS * NACT];   // 1792 floats
    __shared__ alignas(16) float2 sA[NACT][10];  // A (joint6: A*F7r)
    __shared__ alignas(16) float2 sB[NACT][10];  // A@K (joint6: (A@K)*F7r)
    __shared__ alignas(16) float2 sC[NACT][10];  // A@(aa^T)-A (joint6: (..)*F7r)
    __shared__ alignas(16) float2 sT[6][4];      // t, joints 0..5
    __shared__ alignas(16) float2 sT6[10];       // a't[3] b't[3] c't[3] pad

    const int tid = threadIdx.x;
    const int half = n >> 1;                     // B even
    const int g = blockIdx.x * THREADS + tid;

    // ---- per-joint constants ----
    if (tid < NACT) {
        const float* F = ft + tid * 16;
        float A[9], Bm[9], Cm[9];
        #pragma unroll
        for (int r = 0; r < 3; r++)
            #pragma unroll
            for (int c = 0; c < 3; c++)
                A[r * 3 + c] = F[r * 4 + c];
        const float ax = axes[tid * 3 + 0];
        const float ay = axes[tid * 3 + 1];
        const float az = axes[tid * 3 + 2];
        #pragma unroll
        for (int r = 0; r < 3; r++) {
            Bm[r * 3 + 0] = A[r * 3 + 1] * az - A[r * 3 + 2] * ay;
            Bm[r * 3 + 1] = A[r * 3 + 2] * ax - A[r * 3 + 0] * az;
            Bm[r * 3 + 2] = A[r * 3 + 0] * ay - A[r * 3 + 1] * ax;
        }
        #pragma unroll
        for (int r = 0; r < 3; r++) {
            float dp = A[r * 3 + 0] * ax + A[r * 3 + 1] * ay + A[r * 3 + 2] * az;
            Cm[r * 3 + 0] = dp * ax - A[r * 3 + 0];
            Cm[r * 3 + 1] = dp * ay - A[r * 3 + 1];
            Cm[r * 3 + 2] = dp * az - A[r * 3 + 2];
        }
        if (tid < 6) {
            #pragma unroll
            for (int k = 0; k < 9; k++) {
                sA[tid][k] = make_float2(A[k], A[k]);
                sB[tid][k] = make_float2(Bm[k], Bm[k]);
                sC[tid][k] = make_float2(Cm[k], Cm[k]);
            }
            sA[tid][9] = sB[tid][9] = sC[tid][9] = make_float2(0.f, 0.f);
            sT[tid][0] = make_float2(F[3],  F[3]);
            sT[tid][1] = make_float2(F[7],  F[7]);
            sT[tid][2] = make_float2(F[11], F[11]);
            sT[tid][3] = make_float2(0.f, 0.f);
        } else {
            // joint 6: fold F7.  M6*F7 rot = (A+sB+oC)*F7r ; trans = (A f7t + t6) + s(B f7t) + o(C f7t)
            const float* F7 = ft + 7 * 16;
            float F7r[9], f7t[3];
            #pragma unroll
            for (int r = 0; r < 3; r++) {
                #pragma unroll
                for (int c = 0; c < 3; c++)
                    F7r[r * 3 + c] = F7[r * 4 + c];
                f7t[r] = F7[r * 4 + 3];
            }
            float Ap[9], Bp[9], Cp[9];
            #pragma unroll
            for (int r = 0; r < 3; r++)
                #pragma unroll
                for (int c = 0; c < 3; c++) {
                    Ap[r * 3 + c] = A[r * 3 + 0] * F7r[c] + A[r * 3 + 1] * F7r[3 + c] + A[r * 3 + 2] * F7r[6 + c];
                    Bp[r * 3 + c] = Bm[r * 3 + 0] * F7r[c] + Bm[r * 3 + 1] * F7r[3 + c] + Bm[r * 3 + 2] * F7r[6 + c];
                    Cp[r * 3 + c] = Cm[r * 3 + 0] * F7r[c] + Cm[r * 3 + 1] * F7r[3 + c] + Cm[r * 3 + 2] * F7r[6 + c];
                }
            #pragma unroll
            for (int k = 0; k < 9; k++) {
                sA[6][k] = make_float2(Ap[k], Ap[k]);
                sB[6][k] = make_float2(Bp[k], Bp[k]);
                sC[6][k] = make_float2(Cp[k], Cp[k]);
            }
            sA[6][9] = sB[6][9] = sC[6][9] = make_float2(0.f, 0.f);
            #pragma unroll
            for (int r = 0; r < 3; r++) {
                float at = A[r * 3 + 0] * f7t[0] + A[r * 3 + 1] * f7t[1] + A[r * 3 + 2] * f7t[2] + F[r * 4 + 3];
                float bt = Bm[r * 3 + 0] * f7t[0] + Bm[r * 3 + 1] * f7t[1] + Bm[r * 3 + 2] * f7t[2];
                float ct = Cm[r * 3 + 0] * f7t[0] + Cm[r * 3 + 1] * f7t[1] + Cm[r * 3 + 2] * f7t[2];
                sT6[0 + r] = make_float2(at, at);
                sT6[3 + r] = make_float2(bt, bt);
                sT6[6 + r] = make_float2(ct, ct);
            }
            sT6[9] = make_float2(0.f, 0.f);
        }
    }

    // ---- coalesced input stage ----
    // region 0: thetas of elems [blk*T, blk*T+T); region 1: same + half
    {
        const long long total_f = (long long)n * NACT;
        const long long b0 = (long long)blockIdx.x * (THREADS * NACT);
        const long long b1 = b0 + (long long)half * NACT;
        #pragma unroll
        for (int j = 0; j < 2; j++) {   // 224 float4 per region, 128 threads
            int f4 = j * THREADS + tid;
            if (f4 < (THREADS * NACT) / 4) {
                long long g0 = b0 + (long long)f4 * 4;
                long long g1 = b1 + (long long)f4 * 4;
                float4 v0, v1;
                if (g0 + 3 < total_f) v0 = *reinterpret_cast<const float4*>(jp + g0);
                else { v0.x = v0.y = v0.z = v0.w = 0.f; }
                if (g1 + 3 < total_f) v1 = *reinterpret_cast<const float4*>(jp + g1);
                else { v1.x = v1.y = v1.z = v1.w = 0.f; }
                *reinterpret_cast<float4*>(s_in + f4 * 4) = v0;
                *reinterpret_cast<float4*>(s_in + THREADS * NACT + f4 * 4) = v1;
            }
        }
    }
    __syncthreads();

    if (g >= half) return;

    const float* t0p = s_in + tid * NACT;                   // stride 7: conflict-free
    const float* t1p = s_in + THREADS * NACT + tid * NACT;

    u64 Ar[9], At[3], Br[9], Bt[3], Pa_r[9], Pa_t[3], Pb_r[9], Pb_t[3];

    // P0 = M0*M1
    buildM(sA[0], sB[0], sC[0], sT[0], t0p[0], t1p[0], Ar, At);
    buildM(sA[1], sB[1], sC[1], sT[1], t0p[1], t1p[1], Br, Bt);
    amul(Ar, At, Br, Bt, Pa_r, Pa_t);
    // P1 = M2*M3
    buildM(sA[2], sB[2], sC[2], sT[2], t0p[2], t1p[2], Ar, At);
    buildM(sA[3], sB[3], sC[3], sT[3], t0p[3], t1p[3], Br, Bt);
    amul(Ar, At, Br, Bt, Pb_r, Pb_t);
    // Q0 = P0*P1  (into Ar/At)
    amul(Pa_r, Pa_t, Pb_r, Pb_t, Ar, At);
    // P2 = M4*M5  (into Pb)
    buildM(sA[4], sB[4], sC[4], sT[4], t0p[4], t1p[4], Br, Bt);
    buildM(sA[5], sB[5], sC[5], sT[5], t0p[5], t1p[5], Pa_r, Pa_t);
    amul(Br, Bt, Pa_r, Pa_t, Pb_r, Pb_t);
    // M6' = M6*F7 (into Br/Bt)
    buildM6(sA[6], sB[6], sC[6], sT6, t0p[6], t1p[6], Br, Bt);
    // Q1 = P2*M6' (into Pa)
    amul(Pb_r, Pb_t, Br, Bt, Pa_r, Pa_t);
    // T = Q0*Q1   (into Br/Bt)
    amul(Ar, At, Pa_r, Pa_t, Br, Bt);

    float2 rr[9], ot[3];
    #pragma unroll
    for (int k = 0; k < 9; k++) rr[k] = unpack2(Br[k]);
    #pragma unroll
    for (int k = 0; k < 3; k++) ot[k] = unpack2(Bt[k]);

    {
        float4* o0 = reinterpret_cast<float4*>(out + (size_t)g * 16);
        o0[0] = make_float4(rr[0].x, rr[1].x, rr[2].x, ot[0].x);
        o0[1] = make_float4(rr[3].x, rr[4].x, rr[5].x, ot[1].x);
        o0[2] = make_float4(rr[6].x, rr[7].x, rr[8].x, ot[2].x);
        o0[3] = make_float4(0.0f, 0.0f, 0.0f, 1.0f);

        float4* o1 = reinterpret_cast<float4*>(out + (size_t)(g + half) * 16);
        o1[0] = make_float4(rr[0].y, rr[1].y, rr[2].y, ot[0].y);
        o1[1] = make_float4(rr[3].y, rr[4].y, rr[5].y, ot[1].y);
        o1[2] = make_float4(rr[6].y, rr[7].y, rr[8].y, ot[2].y);
        o1[3] = make_float4(0.0f, 0.0f, 0.0f, 1.0f);
    }
}

extern "C" void kernel_launch(void* const* d_in, const int* in_sizes, int n_in,
                              void* d_out, int out_size) {
    const float* jp   = (const float*)d_in[0];  // joint_positions (B,7)
    const float* ft   = (const float*)d_in[1];  // fixed_transforms (8,4,4)
    const float* axes = (const float*)d_in[2];  // joint_axes (7,3)
    float* out = (float*)d_out;
    const int n = in_sizes[0] / NACT;
    const int half = n >> 1;                    // B is even
    const int blocks = (half + THREADS - 1) / THREADS;
    fk_kernel<<<blocks, THREADS>>>(jp, ft, axes, out, n);
}